// round 12
// baseline (speedup 1.0000x reference)
#include <cuda_runtime.h>

#define BB 16
#define TMAX 512
#define DD 512
#define T_FRAMES 4096   // TMAX * MAX_DUR(8)
#define RPB 8           // rows (frames) per block

// Single fused kernel. One block per RPB consecutive (b, frame) rows,
// 128 threads. Prologue: block-redundant scan of ds[b,:] (32KB total,
// L2-broadcast) to find the covering token for each of its RPB frames.
// Body: batched row copy + one-hot map writes, written through past L2
// (__stwt) so the 256MiB output stream neither evicts the L2-resident xs
// nor occupies LTS dirty-line capacity on its way to HBM.
__global__ void __launch_bounds__(128) fused_kernel(
    const float4* __restrict__ xs,   // [B, TMAX, D/4]
    const int*    __restrict__ ds,   // [B, TMAX] int32 (JAX x64 disabled)
    float4* __restrict__ ys,         // [B, T_FRAMES, D/4]
    float4* __restrict__ mp)         // [B, T_FRAMES, TMAX/4]
{
    const int row0 = blockIdx.x * RPB;        // first global row (b*T_FRAMES+f)
    const int b    = row0 >> 12;              // / T_FRAMES
    const int fl0  = row0 & (T_FRAMES - 1);   // LOCAL frame within batch b
    const int k    = threadIdx.x;             // 0..127
    const int lane = k & 31;
    const int w    = k >> 5;                  // warp 0..3

    __shared__ int s_wsum[4];
    __shared__ int s_tok[RPB];

    // ---- Prologue: find covering token for local frames [fl0, fl0+RPB) ----
    // Each thread owns 4 consecutive tokens: 4k .. 4k+3.
    const int4 dv = ((const int4*)(ds + b * TMAX))[k];
    const int lsum = dv.x + dv.y + dv.z + dv.w;

    // inclusive warp scan of per-thread sums
    int v = lsum;
    #pragma unroll
    for (int off = 1; off < 32; off <<= 1) {
        int n = __shfl_up_sync(0xffffffffu, v, off);
        if (lane >= off) v += n;
    }
    const int laneExcl = v - lsum;
    if (lane == 31) s_wsum[w] = v;
    if (k < RPB)    s_tok[k] = -1;
    __syncthreads();

    // exclusive prefix across the 4 warps (branch-free)
    int wExcl = 0;
    #pragma unroll
    for (int j = 0; j < 3; j++)
        wExcl += (j < w) ? s_wsum[j] : 0;

    // walk this thread's 4 tokens; mark any of the block's frames they cover.
    // Intervals are disjoint -> at most one writer per s_tok slot.
    {
        int st = wExcl + laneExcl;
        const int dd4[4] = {dv.x, dv.y, dv.z, dv.w};
        #pragma unroll
        for (int c = 0; c < 4; c++) {
            const int en = st + dd4[c];
            #pragma unroll
            for (int j = 0; j < RPB; j++) {
                const int fl = fl0 + j;       // LOCAL frame index
                if (st <= fl && fl < en) s_tok[j] = 4 * k + c;
            }
            st = en;
        }
    }
    __syncthreads();

    // ---- Body: batched loads then batched write-through stores ----
    int tok[RPB];
    #pragma unroll
    for (int j = 0; j < RPB; j++) tok[j] = s_tok[j];

    float4 yv[RPB];
    #pragma unroll
    for (int j = 0; j < RPB; j++) {
        yv[j] = make_float4(0.f, 0.f, 0.f, 0.f);
        if (tok[j] >= 0)
            yv[j] = xs[((size_t)b * TMAX + tok[j]) * (DD / 4) + k];
    }

    #pragma unroll
    for (int j = 0; j < RPB; j++)
        __stwt(&ys[(size_t)(row0 + j) * (DD / 4) + k], yv[j]);

    #pragma unroll
    for (int j = 0; j < RPB; j++) {
        float4 mv = make_float4(0.f, 0.f, 0.f, 0.f);
        if (tok[j] >= 0 && (tok[j] >> 2) == k)
            ((float*)&mv)[tok[j] & 3] = 1.0f;
        __stwt(&mp[(size_t)(row0 + j) * (TMAX / 4) + k], mv);
    }
}

extern "C" void kernel_launch(void* const* d_in, const int* in_sizes, int n_in,
                              void* d_out, int out_size) {
    const float* xs = (const float*)d_in[0];
    const int*   ds = (const int*)d_in[1];   // int32 (JAX x64 disabled)

    float* out = (float*)d_out;
    float* ys  = out;                                    // [B, T_FRAMES, D]
    float* mp  = out + (size_t)BB * T_FRAMES * DD;       // [B, T_FRAMES, TMAX]

    fused_kernel<<<(BB * T_FRAMES) / RPB, 128>>>(
        (const float4*)xs, ds, (float4*)ys, (float4*)mp);
}

// round 13
// speedup vs baseline: 1.1905x; 1.1905x over previous
#include <cuda_runtime.h>

#define BB 16
#define TMAX 512
#define DD 512
#define T_FRAMES 4096   // TMAX * MAX_DUR(8)
#define RPB 8           // rows (frames) per block

// Single fused kernel. One block per RPB consecutive (b, frame) rows,
// 128 threads. Prologue: block-redundant scan of ds[b,:] (32KB total,
// L2-broadcast) to find the covering token for each of its RPB frames.
// Body: batched row copy + one-hot map writes, streamed through L2 with
// evict-first policy (__stcs): the output stream keeps L2's coalesced
// write-drain path (unlike __stwt, which regressed 8us) but does not
// evict the L2-resident xs (16.7MB, 8x reuse) in steady state.
__global__ void __launch_bounds__(128) fused_kernel(
    const float4* __restrict__ xs,   // [B, TMAX, D/4]
    const int*    __restrict__ ds,   // [B, TMAX] int32 (JAX x64 disabled)
    float4* __restrict__ ys,         // [B, T_FRAMES, D/4]
    float4* __restrict__ mp)         // [B, T_FRAMES, TMAX/4]
{
    const int row0 = blockIdx.x * RPB;        // first global row (b*T_FRAMES+f)
    const int b    = row0 >> 12;              // / T_FRAMES
    const int fl0  = row0 & (T_FRAMES - 1);   // LOCAL frame within batch b
    const int k    = threadIdx.x;             // 0..127
    const int lane = k & 31;
    const int w    = k >> 5;                  // warp 0..3

    __shared__ int s_wsum[4];
    __shared__ int s_tok[RPB];

    // ---- Prologue: find covering token for local frames [fl0, fl0+RPB) ----
    // Each thread owns 4 consecutive tokens: 4k .. 4k+3.
    const int4 dv = ((const int4*)(ds + b * TMAX))[k];
    const int lsum = dv.x + dv.y + dv.z + dv.w;

    // inclusive warp scan of per-thread sums
    int v = lsum;
    #pragma unroll
    for (int off = 1; off < 32; off <<= 1) {
        int n = __shfl_up_sync(0xffffffffu, v, off);
        if (lane >= off) v += n;
    }
    const int laneExcl = v - lsum;
    if (lane == 31) s_wsum[w] = v;
    if (k < RPB)    s_tok[k] = -1;
    __syncthreads();

    // exclusive prefix across the 4 warps (branch-free)
    int wExcl = 0;
    #pragma unroll
    for (int j = 0; j < 3; j++)
        wExcl += (j < w) ? s_wsum[j] : 0;

    // walk this thread's 4 tokens; mark any of the block's frames they cover.
    // Intervals are disjoint -> at most one writer per s_tok slot.
    {
        int st = wExcl + laneExcl;
        const int dd4[4] = {dv.x, dv.y, dv.z, dv.w};
        #pragma unroll
        for (int c = 0; c < 4; c++) {
            const int en = st + dd4[c];
            #pragma unroll
            for (int j = 0; j < RPB; j++) {
                const int fl = fl0 + j;       // LOCAL frame index
                if (st <= fl && fl < en) s_tok[j] = 4 * k + c;
            }
            st = en;
        }
    }
    __syncthreads();

    // ---- Body: batched loads then batched streaming stores ----
    int tok[RPB];
    #pragma unroll
    for (int j = 0; j < RPB; j++) tok[j] = s_tok[j];

    float4 yv[RPB];
    #pragma unroll
    for (int j = 0; j < RPB; j++) {
        yv[j] = make_float4(0.f, 0.f, 0.f, 0.f);
        if (tok[j] >= 0)
            yv[j] = xs[((size_t)b * TMAX + tok[j]) * (DD / 4) + k];
    }

    #pragma unroll
    for (int j = 0; j < RPB; j++)
        __stcs(&ys[(size_t)(row0 + j) * (DD / 4) + k], yv[j]);

    #pragma unroll
    for (int j = 0; j < RPB; j++) {
        float4 mv = make_float4(0.f, 0.f, 0.f, 0.f);
        if (tok[j] >= 0 && (tok[j] >> 2) == k)
            ((float*)&mv)[tok[j] & 3] = 1.0f;
        __stcs(&mp[(size_t)(row0 + j) * (TMAX / 4) + k], mv);
    }
}

extern "C" void kernel_launch(void* const* d_in, const int* in_sizes, int n_in,
                              void* d_out, int out_size) {
    const float* xs = (const float*)d_in[0];
    const int*   ds = (const int*)d_in[1];   // int32 (JAX x64 disabled)

    float* out = (float*)d_out;
    float* ys  = out;                                    // [B, T_FRAMES, D]
    float* mp  = out + (size_t)BB * T_FRAMES * DD;       // [B, T_FRAMES, TMAX]

    fused_kernel<<<(BB * T_FRAMES) / RPB, 128>>>(
        (const float4*)xs, ds, (float4*)ys, (float4*)mp);
}